// round 3
// baseline (speedup 1.0000x reference)
#include <cuda_runtime.h>
#include <math.h>

// e^{u.v} = sum_{a+b+c<=10} u^(a,b,c) v^(a,b,c) / (a!b!c!)   (|u.v|<=1, trunc <3e-8)
// Z_i = sum_f c_f mono_f(u_i) M_f ; W_i = sum_f |f| c_f mono_f(u_i) M_f
// mean H = (1/N) sum_i (log Z_i - W_i/Z_i)  -  N*1e-8
// Single persistent kernel, software grid barriers (all blocks co-resident).

#define KDEG   10
#define NF     286
#define NFP    288          // 9*32
#define NGRP   9
#define TPB    128
#define MAXBLK 148

__device__ float    g_Mp[MAXBLK * NFP];  // per-block raw moment partials
__device__ float2   g_MZW[NFP];          // (c_f*M_f, |f|*c_f*M_f)
__device__ float    g_Hp[MAXBLK];
__device__ unsigned g_bar1;              // zero-init at load; reset each run
__device__ unsigned g_bar2;
__device__ unsigned g_ticket;

__device__ __forceinline__ void load_unit(const float* __restrict__ vel, int i,
                                          float& x, float& y, float& z) {
    x = vel[3 * i + 0];
    y = vel[3 * i + 1];
    z = vel[3 * i + 2];
    float nrm = sqrtf(x * x + y * y + z * z);
    float inv = 1.0f / (nrm + 1e-6f);
    x *= inv; y *= inv; z *= inv;
}

// Butterfly compaction: 32 lane-local values -> lane l holds warp-sum of value l.
__device__ __forceinline__ float bfly32(float (&v)[32], int lane) {
#pragma unroll
    for (int m = 16; m >= 1; m >>= 1) {
        bool hi = (lane & m) != 0;
#pragma unroll
        for (int k = 0; k < 16; k++) {
            if (k < m) {
                float keep = hi ? v[k + m] : v[k];
                float send = hi ? v[k] : v[k + m];
                v[k] = keep + __shfl_xor_sync(0xffffffffu, send, m);
            }
        }
    }
    return v[0];
}

__device__ __forceinline__ void grid_barrier(unsigned* bar, int nblk) {
    __syncthreads();
    if (threadIdx.x == 0) {
        __threadfence();
        atomicAdd(bar, 1u);
        while (*(volatile unsigned*)bar < (unsigned)nblk) { }
        __threadfence();
    }
    __syncthreads();
}

__global__ void __launch_bounds__(TPB)
fused_kernel(const float* __restrict__ vel, float* __restrict__ out,
             int N, int nblk) {
    __shared__ float  s4[4][NFP];
    __shared__ float2 sM[NFP];
    __shared__ float  rs[4];
    __shared__ int    islast;

    int tid  = threadIdx.x;
    int lane = tid & 31;
    int warp = tid >> 5;

    // ---------- Phase 1: per-block moment partials ----------
    float acc[NGRP];
#pragma unroll
    for (int g = 0; g < NGRP; g++) acc[g] = 0.f;

    for (int base = blockIdx.x * TPB; base < N; base += nblk * TPB) {
        int i = base + tid;
        float x = 0.f, y = 0.f, z = 0.f, w = 0.f;
        if (i < N) { load_unit(vel, i, x, y, z); w = 1.0f; }

        float px[KDEG + 1], py[KDEG + 1], pz[KDEG + 1];
        px[0] = w; py[0] = 1.0f; pz[0] = 1.0f;     // w masks inactive lanes
#pragma unroll
        for (int d = 1; d <= KDEG; d++) {
            px[d] = px[d - 1] * x;
            py[d] = py[d - 1] * y;
            pz[d] = pz[d - 1] * z;
        }

        float v[32];
        int idx = 0;
#pragma unroll
        for (int a = 0; a <= KDEG; a++) {
#pragma unroll
            for (int b = 0; b <= KDEG - a; b++) {
                float xy = px[a] * py[b];
#pragma unroll
                for (int c = 0; c <= KDEG - a - b; c++) {
                    v[idx & 31] = xy * pz[c];
                    if ((idx & 31) == 31) acc[idx >> 5] += bfly32(v, lane);
                    idx++;
                }
            }
        }
        v[30] = 0.f; v[31] = 0.f;                   // pad group 8 (286 -> 288)
        acc[8] += bfly32(v, lane);
    }

#pragma unroll
    for (int g = 0; g < NGRP; g++) s4[warp][g * 32 + lane] = acc[g];
    __syncthreads();
    for (int f = tid; f < NFP; f += TPB)
        g_Mp[blockIdx.x * NFP + f] = s4[0][f] + s4[1][f] + s4[2][f] + s4[3][f];

    grid_barrier(&g_bar1, nblk);

    // ---------- Phase 2: global moment reduce + coefficient folding ----------
    int nwarp = nblk * (TPB / 32);
    for (int f = blockIdx.x * (TPB / 32) + warp; f < NFP; f += nwarp) {
        float a = 0.f;
        for (int b = lane; b < nblk; b += 32) a += g_Mp[b * NFP + f];
        a += __shfl_xor_sync(0xffffffffu, a, 16);
        a += __shfl_xor_sync(0xffffffffu, a, 8);
        a += __shfl_xor_sync(0xffffffffu, a, 4);
        a += __shfl_xor_sync(0xffffffffu, a, 2);
        a += __shfl_xor_sync(0xffffffffu, a, 1);
        if (lane == 0) {
            float cf = 0.f, deg = 0.f;
            if (f < NF) {
                int rem = f, ia = 0, ib = 0;
                for (ia = 0; ia <= KDEG; ia++) {
                    int cnt = (KDEG + 1 - ia) * (KDEG + 2 - ia) / 2;
                    if (rem < cnt) break;
                    rem -= cnt;
                }
                for (ib = 0; ib <= KDEG - ia; ib++) {
                    int cnt = KDEG + 1 - ia - ib;
                    if (rem < cnt) break;
                    rem -= cnt;
                }
                int ic = rem;
                float fa = 1.f, fb = 1.f, fc = 1.f;
                for (int t = 2; t <= ia; t++) fa *= (float)t;
                for (int t = 2; t <= ib; t++) fb *= (float)t;
                for (int t = 2; t <= ic; t++) fc *= (float)t;
                cf  = 1.0f / (fa * fb * fc);
                deg = (float)(ia + ib + ic);
            }
            g_MZW[f] = make_float2(cf * a, cf * deg * a);
        }
    }

    grid_barrier(&g_bar2, nblk);

    // ---------- Phase 3: per-point entropy ----------
    for (int f = tid; f < NFP; f += TPB) sM[f] = g_MZW[f];
    __syncthreads();
    const unsigned long long* sM64 = reinterpret_cast<const unsigned long long*>(sM);

    float H = 0.f;
    for (int base = blockIdx.x * TPB; base < N; base += nblk * TPB) {
        int i = base + tid;
        if (i >= N) break;
        float x, y, z;
        load_unit(vel, i, x, y, z);

        float px[KDEG + 1], py[KDEG + 1], pz[KDEG + 1];
        px[0] = 1.0f; py[0] = 1.0f; pz[0] = 1.0f;
#pragma unroll
        for (int d = 1; d <= KDEG; d++) {
            px[d] = px[d - 1] * x;
            py[d] = py[d - 1] * y;
            pz[d] = pz[d - 1] * z;
        }

        unsigned long long acc2 = 0ull;   // packed (Z, W)
        int idx = 0;
#pragma unroll
        for (int a = 0; a <= KDEG; a++) {
#pragma unroll
            for (int b = 0; b <= KDEG - a; b++) {
                float xy = px[a] * py[b];
#pragma unroll
                for (int c = 0; c <= KDEG - a - b; c++) {
                    float mono = xy * pz[c];
                    unsigned int mu = __float_as_uint(mono);
                    unsigned long long mm;
                    asm("mov.b64 %0, {%1, %1};" : "=l"(mm) : "r"(mu));
                    asm("fma.rn.f32x2 %0, %1, %2, %3;"
                        : "=l"(acc2) : "l"(mm), "l"(sM64[idx]), "l"(acc2));
                    idx++;
                }
            }
        }
        unsigned int zu, wu;
        asm("mov.b64 {%0, %1}, %2;" : "=r"(zu), "=r"(wu) : "l"(acc2));
        float Z = __uint_as_float(zu);
        float W = __uint_as_float(wu);
        H += logf(Z) - W / Z;
    }

    H += __shfl_xor_sync(0xffffffffu, H, 16);
    H += __shfl_xor_sync(0xffffffffu, H, 8);
    H += __shfl_xor_sync(0xffffffffu, H, 4);
    H += __shfl_xor_sync(0xffffffffu, H, 2);
    H += __shfl_xor_sync(0xffffffffu, H, 1);
    if (lane == 0) rs[warp] = H;
    __syncthreads();

    // ---------- Phase 4: last block finalizes ----------
    if (tid == 0) {
        g_Hp[blockIdx.x] = rs[0] + rs[1] + rs[2] + rs[3];
        __threadfence();
        unsigned t = atomicAdd(&g_ticket, 1u);
        islast = (t == (unsigned)(nblk - 1));
    }
    __syncthreads();

    if (islast) {
        __threadfence();
        float a = 0.f;
        for (int b = tid; b < nblk; b += TPB) a += g_Hp[b];
        a += __shfl_xor_sync(0xffffffffu, a, 16);
        a += __shfl_xor_sync(0xffffffffu, a, 8);
        a += __shfl_xor_sync(0xffffffffu, a, 4);
        a += __shfl_xor_sync(0xffffffffu, a, 2);
        a += __shfl_xor_sync(0xffffffffu, a, 1);
        if (lane == 0) rs[warp] = a;
        __syncthreads();
        if (tid == 0) {
            float total = rs[0] + rs[1] + rs[2] + rs[3];
            out[0] = total / (float)N - (float)N * 1e-8f;
            // reset for next graph replay (all blocks are past both barriers)
            g_bar1 = 0u; g_bar2 = 0u; g_ticket = 0u;
        }
    }
}

extern "C" void kernel_launch(void* const* d_in, const int* in_sizes, int n_in,
                              void* d_out, int out_size) {
    const float* vel = (const float*)d_in[0];   // velocities (N,3); positions unused
    int N = in_sizes[0] / 3;
    int nblk = (N + TPB - 1) / TPB;
    if (nblk > MAXBLK) nblk = MAXBLK;           // all blocks must be co-resident
    if (nblk < 1) nblk = 1;

    fused_kernel<<<nblk, TPB>>>(vel, (float*)d_out, N, nblk);
}